// round 1
// baseline (speedup 1.0000x reference)
#include <cuda_runtime.h>

// Problem constants (fixed shapes from the reference)
#define BB   8
#define NN   12288
#define NTOK 3072
#define CC   256
#define COUT 512
#define HH   128
#define WW   96
#define HWC  (HH*WW)        // 12288 cells
#define H2   64
#define W2   48
#define HW2  (H2*W2)        // 3072 cells
#define MROWS (BB*NTOK)     // 24576

// ---------------- scratch (device globals; no allocation allowed) ----------
__device__ float g_map [(size_t)BB*HWC*CC];   // (b, cell, c) token2map sums -> normalized map
__device__ float g_cnt [BB*HWC];
__device__ float g_conv[(size_t)BB*HW2*CC];   // depthwise conv output (b, cell2, c)
__device__ float g_num [(size_t)BB*NTOK*CC];  // fused numerator (skip*dw + map) * w
__device__ float g_den [BB*NTOK];
__device__ float g_xd  [(size_t)BB*NTOK*CC];  // pre-BN1 xd
__device__ float g_stats1[2*CC];              // sum, sumsq per C channel
__device__ float g_stats2[2*COUT];            // sum, sumsq per CO channel
__device__ float g_wp  [COUT*CC];             // BN1-folded weights
__device__ float g_bias[COUT];                // BN1-folded bias
__device__ float g_a2  [COUT];                // BN2 scale
__device__ float g_d2  [COUT];                // BN2 shift

// ---------------- helpers ----------------
__device__ __forceinline__ int grid_cell(float lx, float ly, int h, int w) {
    // matches: clip(loc,-1,1); round(0.5*(loc+1)*w - 0.5) with round-half-even,
    // then clip to [0, w-1]. Use _rn intrinsics to forbid FMA contraction.
    lx = fminf(fmaxf(lx, -1.0f), 1.0f);
    ly = fminf(fmaxf(ly, -1.0f), 1.0f);
    float fx = __fadd_rn(__fmul_rn(__fmul_rn(0.5f, __fadd_rn(lx, 1.0f)), (float)w), -0.5f);
    float fy = __fadd_rn(__fmul_rn(__fmul_rn(0.5f, __fadd_rn(ly, 1.0f)), (float)h), -0.5f);
    int xi = __float2int_rn(fx);  // cvt.rni = round-to-nearest-even, matches jnp.round
    int yi = __float2int_rn(fy);
    xi = min(max(xi, 0), w - 1);
    yi = min(max(yi, 0), h - 1);
    return xi + yi * w;
}

// ---------------- kernels ----------------
__global__ void k_zero() {
    size_t i = (size_t)blockIdx.x * blockDim.x + threadIdx.x;
    size_t stride = (size_t)gridDim.x * blockDim.x;
    const float4 z = make_float4(0.f, 0.f, 0.f, 0.f);
    float4* m4 = (float4*)g_map;
    for (size_t k = i; k < (size_t)BB*HWC*CC/4; k += stride) m4[k] = z;
    float4* n4 = (float4*)g_num;
    for (size_t k = i; k < (size_t)BB*NTOK*CC/4; k += stride) n4[k] = z;
    float4* c4 = (float4*)g_cnt;
    for (size_t k = i; k < (size_t)(BB*HWC/4); k += stride) c4[k] = z;
    float4* d4 = (float4*)g_den;
    for (size_t k = i; k < (size_t)(BB*NTOK/4); k += stride) d4[k] = z;
    if (i < 2*CC)  g_stats1[i] = 0.f;
    if (i < 2*COUT) g_stats2[i] = 0.f;
}

// token2map scatter: one block per (b, token), threads = channels
__global__ void k_scatter_map(const float* __restrict__ x,
                              const float* __restrict__ loc,
                              const int*   __restrict__ idx_agg) {
    int blk = blockIdx.x;          // b*N + i
    int b = blk / NN;
    int c = threadIdx.x;
    float lx = loc[2*blk + 0], ly = loc[2*blk + 1];
    int cell = grid_cell(lx, ly, HH, WW);
    int src = idx_agg[blk];
    float v = x[((size_t)b*NN + src)*CC + c];
    atomicAdd(&g_map[((size_t)b*HWC + cell)*CC + c], v);
    if (c == 0) atomicAdd(&g_cnt[b*HWC + cell], 1.0f);
}

// normalize: x_map = sum / (count + 1e-6)
__global__ void k_norm_map() {
    int blk = blockIdx.x;          // b*HW + cell
    float inv = 1.0f / (g_cnt[blk] + 1e-6f);
    float4* p = (float4*)&g_map[(size_t)blk * CC];
    float4 v = p[threadIdx.x];
    v.x *= inv; v.y *= inv; v.z *= inv; v.w *= inv;
    p[threadIdx.x] = v;
}

// depthwise 3x3 stride-2 conv, pad 1; one block per output pixel, threads = channels
__global__ void k_dwconv(const float* __restrict__ wc) {
    int blk = blockIdx.x;          // b*HW2 + cell2
    int b = blk / HW2;
    int cell = blk - b * HW2;
    int y2 = cell / W2, x2 = cell - y2 * W2;
    int c = threadIdx.x;
    float acc = 0.f;
    #pragma unroll
    for (int ky = 0; ky < 3; ky++) {
        int y = 2*y2 - 1 + ky;
        if ((unsigned)y >= HH) continue;
        #pragma unroll
        for (int kx = 0; kx < 3; kx++) {
            int xx = 2*x2 - 1 + kx;
            if ((unsigned)xx >= WW) continue;
            acc += g_map[((size_t)b*HWC + y*WW + xx)*CC + c] * wc[c*9 + ky*3 + kx];
        }
    }
    g_conv[(size_t)blk * CC + c] = acc;
}

// fused map2token + token_downup scatter (shared seg ids & denominators):
//   num[seg,c] += (x[src,c]*dw_skip[c] + conv[cell2,c]) * w ;  den[seg] += w
__global__ void k_scatter_tok(const float* __restrict__ x,
                              const float* __restrict__ loc,
                              const int*   __restrict__ idx_agg,
                              const int*   __restrict__ idx_agg_t,
                              const float* __restrict__ wgt_t,
                              const float* __restrict__ dw_skip) {
    int blk = blockIdx.x;          // b*N + i
    int b = blk / NN;
    int c = threadIdx.x;
    float lx = loc[2*blk + 0], ly = loc[2*blk + 1];
    int cell2 = grid_cell(lx, ly, H2, W2);
    int src = idx_agg[blk];
    int tgt = idx_agg_t[blk];
    float w = wgt_t[blk];
    float feat = g_conv[((size_t)b*HW2 + cell2)*CC + c];
    float xv   = x[((size_t)b*NN + src)*CC + c];
    float val  = (xv * dw_skip[c] + feat) * w;
    atomicAdd(&g_num[((size_t)b*NTOK + tgt)*CC + c], val);
    if (c == 0) atomicAdd(&g_den[b*NTOK + tgt], w);
}

// xd = num/(den+1e-6); accumulate BN1 per-channel sum & sumsq
#define RPB1 96
__global__ void k_bn1_stats() {
    int c = threadIdx.x;
    int r0 = blockIdx.x * RPB1;
    float s = 0.f, s2 = 0.f;
    for (int r = r0; r < r0 + RPB1; ++r) {
        float rden = 1.0f / (g_den[r] + 1e-6f);
        float v = g_num[(size_t)r*CC + c] * rden;
        g_xd[(size_t)r*CC + c] = v;
        s += v; s2 += v * v;
    }
    atomicAdd(&g_stats1[c], s);
    atomicAdd(&g_stats1[CC + c], s2);
}

// fold BN1 into the 1x1 conv: W'[o,c] = W[o,c]*a_c ; bias'[o] = sum_c d_c*W[o,c]
__global__ void k_fold(const float* __restrict__ conv_w,
                       const float* __restrict__ g1,
                       const float* __restrict__ b1) {
    __shared__ float red[CC];
    int o = blockIdx.x, c = threadIdx.x;
    const float inv = 1.0f / (float)MROWS;
    float mean = g_stats1[c] * inv;
    float var  = g_stats1[CC + c] * inv - mean * mean;
    float a = g1[c] * rsqrtf(var + 1e-5f);
    float d = b1[c] - mean * a;
    float w = conv_w[o*CC + c];
    g_wp[o*CC + c] = w * a;
    red[c] = d * w;
    __syncthreads();
    for (int s = CC/2; s > 0; s >>= 1) {
        if (c < s) red[c] += red[c + s];
        __syncthreads();
    }
    if (c == 0) g_bias[o] = red[0];
}

// GEMM: Y[m,o] = xd[m,:] . wp[o,:] + bias[o]   (M=24576, N=512, K=256)
// 64x64 block tile, BK=16, 4x4 per thread, 256 threads.
__global__ void __launch_bounds__(256) k_gemm(float* __restrict__ out) {
    __shared__ float As[16][64];
    __shared__ float Bs[16][64];
    const int m0 = blockIdx.y * 64;
    const int o0 = blockIdx.x * 64;
    const int t  = threadIdx.x;
    const int tx = t & 15, ty = t >> 4;
    const int lrow = t >> 2;           // 0..63
    const int lcol = (t & 3) * 4;      // 0,4,8,12
    float acc[4][4] = {};
    for (int k0 = 0; k0 < CC; k0 += 16) {
        float4 av = *(const float4*)&g_xd[(size_t)(m0 + lrow)*CC + k0 + lcol];
        float4 bv = *(const float4*)&g_wp[(size_t)(o0 + lrow)*CC + k0 + lcol];
        As[lcol+0][lrow] = av.x; As[lcol+1][lrow] = av.y;
        As[lcol+2][lrow] = av.z; As[lcol+3][lrow] = av.w;
        Bs[lcol+0][lrow] = bv.x; Bs[lcol+1][lrow] = bv.y;
        Bs[lcol+2][lrow] = bv.z; Bs[lcol+3][lrow] = bv.w;
        __syncthreads();
        #pragma unroll
        for (int k = 0; k < 16; k++) {
            float4 a4 = *(const float4*)&As[k][ty*4];
            float4 b4 = *(const float4*)&Bs[k][tx*4];
            float a_[4] = {a4.x, a4.y, a4.z, a4.w};
            float b_[4] = {b4.x, b4.y, b4.z, b4.w};
            #pragma unroll
            for (int i = 0; i < 4; i++)
                #pragma unroll
                for (int j = 0; j < 4; j++)
                    acc[i][j] += a_[i] * b_[j];
        }
        __syncthreads();
    }
    float bj[4];
    #pragma unroll
    for (int j = 0; j < 4; j++) bj[j] = g_bias[o0 + tx*4 + j];
    #pragma unroll
    for (int i = 0; i < 4; i++) {
        float4 r;
        r.x = acc[i][0] + bj[0];
        r.y = acc[i][1] + bj[1];
        r.z = acc[i][2] + bj[2];
        r.w = acc[i][3] + bj[3];
        *(float4*)&out[(size_t)(m0 + ty*4 + i)*COUT + o0 + tx*4] = r;
    }
}

// BN2 stats over d_out rows
#define RPB2 128
__global__ void k_bn2_stats(const float* __restrict__ out) {
    int o = threadIdx.x;               // 512 threads
    int r0 = blockIdx.x * RPB2;
    float s = 0.f, s2 = 0.f;
    for (int r = r0; r < r0 + RPB2; ++r) {
        float v = out[(size_t)r*COUT + o];
        s += v; s2 += v * v;
    }
    atomicAdd(&g_stats2[o], s);
    atomicAdd(&g_stats2[COUT + o], s2);
}

__global__ void k_fold2(const float* __restrict__ g2, const float* __restrict__ b2) {
    int o = threadIdx.x;
    const float inv = 1.0f / (float)MROWS;
    float mean = g_stats2[o] * inv;
    float var  = g_stats2[COUT + o] * inv - mean * mean;
    float a = g2[o] * rsqrtf(var + 1e-5f);
    g_a2[o] = a;
    g_d2[o] = b2[o] - mean * a;
}

// BN2 apply + relu, in place on d_out (float4 over 4 consecutive channels)
__global__ void k_bn2_apply(float* __restrict__ out) {
    size_t idx4 = (size_t)blockIdx.x * blockDim.x + threadIdx.x; // over M*CO/4
    int o = (int)(idx4 & (COUT/4 - 1)) * 4;
    float4 v = ((float4*)out)[idx4];
    v.x = fmaxf(0.f, v.x * g_a2[o+0] + g_d2[o+0]);
    v.y = fmaxf(0.f, v.y * g_a2[o+1] + g_d2[o+1]);
    v.z = fmaxf(0.f, v.z * g_a2[o+2] + g_d2[o+2]);
    v.w = fmaxf(0.f, v.w * g_a2[o+3] + g_d2[o+3]);
    ((float4*)out)[idx4] = v;
}

// ---------------- launch ----------------
extern "C" void kernel_launch(void* const* d_in, const int* in_sizes, int n_in,
                              void* d_out, int out_size) {
    const float* x     = (const float*)d_in[0];   // (B,N,C)
    const float* loc   = (const float*)d_in[1];   // (B,N,2)
    const int*   idxa  = (const int*)  d_in[2];   // (B,N)
    // d_in[3] agg_weight: unused by reference
    // d_in[4] x_t: unused (only provides NT)
    const int*   idxat = (const int*)  d_in[5];   // (B,N)
    const float* wt    = (const float*)d_in[6];   // (B,N,1)
    // d_in[7] H, d_in[8] W: compile-time constants
    const float* dwc   = (const float*)d_in[9];   // (C,1,3,3)
    const float* dws   = (const float*)d_in[10];  // (C,1,1,1)
    const float* g1    = (const float*)d_in[11];
    const float* b1    = (const float*)d_in[12];
    const float* cw    = (const float*)d_in[13];  // (CO,C)
    const float* g2    = (const float*)d_in[14];
    const float* b2    = (const float*)d_in[15];
    float* out = (float*)d_out;

    k_zero<<<2048, 256>>>();
    k_scatter_map<<<BB*NN, CC>>>(x, loc, idxa);
    k_norm_map<<<BB*HWC, CC/4>>>();
    k_dwconv<<<BB*HW2, CC>>>(dwc);
    k_scatter_tok<<<BB*NN, CC>>>(x, loc, idxa, idxat, wt, dws);
    k_bn1_stats<<<MROWS/RPB1, CC>>>();
    k_fold<<<COUT, CC>>>(cw, g1, b1);
    k_gemm<<<dim3(COUT/64, MROWS/64), 256>>>(out);
    k_bn2_stats<<<MROWS/RPB2, COUT>>>(out);
    k_fold2<<<1, COUT>>>(g2, b2);
    k_bn2_apply<<<(MROWS*COUT/4)/256, 256>>>(out);
}

// round 3
// speedup vs baseline: 1.4671x; 1.4671x over previous
#include <cuda_runtime.h>
#include <cuda_bf16.h>
#include <cstdint>

// Problem constants (fixed shapes from the reference)
#define BB   8
#define NN   12288
#define NTOK 3072
#define CC   256
#define COUT 512
#define HH   128
#define WW   96
#define HWC  (HH*WW)        // 12288 cells
#define H2   64
#define W2   48
#define HW2  (H2*W2)        // 3072 cells
#define MROWS (BB*NTOK)     // 24576

// ---------------- scratch (device globals; no allocation allowed) ----------
__device__ float g_map [(size_t)BB*HWC*CC];   // (b, cell, c) token2map sums
__device__ float g_cnt [BB*HWC];              // counts -> reciprocal counts
__device__ float g_conv[(size_t)BB*HW2*CC];   // depthwise conv output (b, cell2, c)
__device__ float g_num [(size_t)BB*NTOK*CC];  // fused numerator (skip*dw + map) * w
__device__ float g_den [BB*NTOK];
__device__ float g_stats1[2*CC];              // sum, sumsq per C channel
__device__ float g_stats2[2*COUT];            // sum, sumsq per CO channel
__device__ float g_wp  [COUT*CC];             // BN1-folded weights
__device__ float g_bias[COUT];                // BN1-folded bias
__device__ float g_a2  [COUT];                // BN2 scale
__device__ float g_d2  [COUT];                // BN2 shift

// packed bf16 operands: A2 = [Ahi | Alo] per row (M x 512), B2 = [Bhi | Blo] (512 x 512)
__device__ __align__(16) __nv_bfloat16 g_A2[(size_t)MROWS*512];
__device__ __align__(16) __nv_bfloat16 g_B2[(size_t)COUT*512];

// ---------------- helpers ----------------
__device__ __forceinline__ uint32_t smem_to_u32(const void* p) {
    uint32_t a;
    asm("{ .reg .u64 t; cvta.to.shared.u64 t, %1; cvt.u32.u64 %0, t; }" : "=r"(a) : "l"(p));
    return a;
}
__device__ __forceinline__ int grid_cell(float lx, float ly, int h, int w) {
    lx = fminf(fmaxf(lx, -1.0f), 1.0f);
    ly = fminf(fmaxf(ly, -1.0f), 1.0f);
    float fx = __fadd_rn(__fmul_rn(__fmul_rn(0.5f, __fadd_rn(lx, 1.0f)), (float)w), -0.5f);
    float fy = __fadd_rn(__fmul_rn(__fmul_rn(0.5f, __fadd_rn(ly, 1.0f)), (float)h), -0.5f);
    int xi = __float2int_rn(fx);   // round-to-nearest-even matches jnp.round
    int yi = __float2int_rn(fy);
    xi = min(max(xi, 0), w - 1);
    yi = min(max(yi, 0), h - 1);
    return xi + yi * w;
}
// SW128 swizzle (Swizzle<3,4,3>) on within-tile byte offsets (128B rows)
__device__ __forceinline__ int swz(int byte) { return byte ^ ((byte >> 3) & 0x70); }

__device__ __forceinline__ void cp16(uint32_t s, const void* g) {
    asm volatile("cp.async.cg.shared.global [%0], [%1], 16;" :: "r"(s), "l"(g));
}
__device__ __forceinline__ void ldmx4(uint32_t* r, uint32_t addr) {
    asm volatile("ldmatrix.sync.aligned.m8n8.x4.shared.b16 {%0,%1,%2,%3}, [%4];"
        : "=r"(r[0]), "=r"(r[1]), "=r"(r[2]), "=r"(r[3]) : "r"(addr));
}
__device__ __forceinline__ void mma16816(float* c, const uint32_t* a, const uint32_t* b) {
    asm volatile("mma.sync.aligned.m16n8k16.row.col.f32.bf16.bf16.f32 "
        "{%0,%1,%2,%3}, {%4,%5,%6,%7}, {%8,%9}, {%0,%1,%2,%3};"
        : "+f"(c[0]), "+f"(c[1]), "+f"(c[2]), "+f"(c[3])
        : "r"(a[0]), "r"(a[1]), "r"(a[2]), "r"(a[3]), "r"(b[0]), "r"(b[1]));
}

// ---------------- kernels ----------------
__global__ void k_zero() {
    size_t i = (size_t)blockIdx.x * blockDim.x + threadIdx.x;
    size_t stride = (size_t)gridDim.x * blockDim.x;
    const float4 z = make_float4(0.f, 0.f, 0.f, 0.f);
    float4* m4 = (float4*)g_map;
    for (size_t k = i; k < (size_t)BB*HWC*CC/4; k += stride) m4[k] = z;
    float4* n4 = (float4*)g_num;
    for (size_t k = i; k < (size_t)BB*NTOK*CC/4; k += stride) n4[k] = z;
    float4* c4 = (float4*)g_cnt;
    for (size_t k = i; k < (size_t)(BB*HWC/4); k += stride) c4[k] = z;
    float4* d4 = (float4*)g_den;
    for (size_t k = i; k < (size_t)(BB*NTOK/4); k += stride) d4[k] = z;
    if (i < 2*CC)  g_stats1[i] = 0.f;
    if (i < 2*COUT) g_stats2[i] = 0.f;
}

__global__ void k_scatter_map(const float* __restrict__ x,
                              const float* __restrict__ loc,
                              const int*   __restrict__ idx_agg) {
    int blk = blockIdx.x;          // b*N + i
    int b = blk / NN;
    int c = threadIdx.x;
    float lx = loc[2*blk + 0], ly = loc[2*blk + 1];
    int cell = grid_cell(lx, ly, HH, WW);
    int src = idx_agg[blk];
    float v = x[((size_t)b*NN + src)*CC + c];
    atomicAdd(&g_map[((size_t)b*HWC + cell)*CC + c], v);
    if (c == 0) atomicAdd(&g_cnt[b*HWC + cell], 1.0f);
}

__global__ void k_invcnt() {
    int i = blockIdx.x * blockDim.x + threadIdx.x;
    if (i < BB*HWC) g_cnt[i] = 1.0f / (g_cnt[i] + 1e-6f);
}

// depthwise 3x3 stride-2 conv with fused count-normalization
__global__ void k_dwconv(const float* __restrict__ wc) {
    int blk = blockIdx.x;          // b*HW2 + cell2
    int b = blk / HW2;
    int cell = blk - b * HW2;
    int y2 = cell / W2, x2 = cell - y2 * W2;
    int c = threadIdx.x;
    float acc = 0.f;
    #pragma unroll
    for (int ky = 0; ky < 3; ky++) {
        int y = 2*y2 - 1 + ky;
        if ((unsigned)y >= HH) continue;
        #pragma unroll
        for (int kx = 0; kx < 3; kx++) {
            int xx = 2*x2 - 1 + kx;
            if ((unsigned)xx >= WW) continue;
            int ci = b*HWC + y*WW + xx;
            float iv = __ldg(&g_cnt[ci]);
            acc += g_map[(size_t)ci*CC + c] * (iv * wc[c*9 + ky*3 + kx]);
        }
    }
    g_conv[(size_t)blk * CC + c] = acc;
}

__global__ void k_scatter_tok(const float* __restrict__ x,
                              const float* __restrict__ loc,
                              const int*   __restrict__ idx_agg,
                              const int*   __restrict__ idx_agg_t,
                              const float* __restrict__ wgt_t,
                              const float* __restrict__ dw_skip) {
    int blk = blockIdx.x;          // b*N + i
    int b = blk / NN;
    int c = threadIdx.x;
    float lx = loc[2*blk + 0], ly = loc[2*blk + 1];
    int cell2 = grid_cell(lx, ly, H2, W2);
    int src = idx_agg[blk];
    int tgt = idx_agg_t[blk];
    float w = wgt_t[blk];
    float feat = g_conv[((size_t)b*HW2 + cell2)*CC + c];
    float xv   = x[((size_t)b*NN + src)*CC + c];
    float val  = (xv * dw_skip[c] + feat) * w;
    atomicAdd(&g_num[((size_t)b*NTOK + tgt)*CC + c], val);
    if (c == 0) atomicAdd(&g_den[b*NTOK + tgt], w);
}

// BN1 per-channel stats of xd = num/(den+eps) (no materialization)
#define RPB1 96
__global__ void k_bn1_stats() {
    int c = threadIdx.x;
    int r0 = blockIdx.x * RPB1;
    float s = 0.f, s2 = 0.f;
    for (int r = r0; r < r0 + RPB1; ++r) {
        float rden = 1.0f / (g_den[r] + 1e-6f);
        float v = g_num[(size_t)r*CC + c] * rden;
        s += v; s2 += v * v;
    }
    atomicAdd(&g_stats1[c], s);
    atomicAdd(&g_stats1[CC + c], s2);
}

// fold BN1 into the 1x1 conv: W'[o,c] = W[o,c]*a_c ; bias'[o] = sum_c d_c*W[o,c]
__global__ void k_fold(const float* __restrict__ conv_w,
                       const float* __restrict__ g1,
                       const float* __restrict__ b1) {
    __shared__ float red[CC];
    int o = blockIdx.x, c = threadIdx.x;
    const float inv = 1.0f / (float)MROWS;
    float mean = g_stats1[c] * inv;
    float var  = g_stats1[CC + c] * inv - mean * mean;
    float a = g1[c] * rsqrtf(var + 1e-5f);
    float d = b1[c] - mean * a;
    float w = conv_w[o*CC + c];
    g_wp[o*CC + c] = w * a;
    red[c] = d * w;
    __syncthreads();
    for (int s = CC/2; s > 0; s >>= 1) {
        if (c < s) red[c] += red[c + s];
        __syncthreads();
    }
    if (c == 0) g_bias[o] = red[0];
}

// pack A2 = [bf16_hi(xd) | bf16_lo(xd)] row-major M x 512
__global__ void k_packA() {
    int idx = blockIdx.x * 256 + threadIdx.x;   // MROWS*32
    int m = idx >> 5, u = idx & 31;
    float rden = 1.0f / (g_den[m] + 1e-6f);
    const float4* src = (const float4*)&g_num[(size_t)m*CC + u*8];
    float4 v0 = src[0], v1 = src[1];
    float vv[8] = {v0.x, v0.y, v0.z, v0.w, v1.x, v1.y, v1.z, v1.w};
    uint32_t hp[4], lp[4];
    #pragma unroll
    for (int j = 0; j < 4; j++) {
        float e0 = vv[2*j] * rden, e1 = vv[2*j+1] * rden;
        __nv_bfloat16 h0 = __float2bfloat16(e0), h1 = __float2bfloat16(e1);
        __nv_bfloat16 l0 = __float2bfloat16(e0 - __bfloat162float(h0));
        __nv_bfloat16 l1 = __float2bfloat16(e1 - __bfloat162float(h1));
        hp[j] = (uint32_t)__bfloat16_as_ushort(h0) | ((uint32_t)__bfloat16_as_ushort(h1) << 16);
        lp[j] = (uint32_t)__bfloat16_as_ushort(l0) | ((uint32_t)__bfloat16_as_ushort(l1) << 16);
    }
    size_t base = (size_t)m * 512 + u*8;
    *(uint4*)&g_A2[base]       = make_uint4(hp[0], hp[1], hp[2], hp[3]);
    *(uint4*)&g_A2[base + 256] = make_uint4(lp[0], lp[1], lp[2], lp[3]);
}

// pack B2 = [bf16_hi(wp) | bf16_lo(wp)] row-major CO x 512
__global__ void k_packB() {
    int idx = blockIdx.x * 256 + threadIdx.x;   // COUT*32
    int o = idx >> 5, u = idx & 31;
    const float4* src = (const float4*)&g_wp[(size_t)o*CC + u*8];
    float4 v0 = src[0], v1 = src[1];
    float vv[8] = {v0.x, v0.y, v0.z, v0.w, v1.x, v1.y, v1.z, v1.w};
    uint32_t hp[4], lp[4];
    #pragma unroll
    for (int j = 0; j < 4; j++) {
        float e0 = vv[2*j], e1 = vv[2*j+1];
        __nv_bfloat16 h0 = __float2bfloat16(e0), h1 = __float2bfloat16(e1);
        __nv_bfloat16 l0 = __float2bfloat16(e0 - __bfloat162float(h0));
        __nv_bfloat16 l1 = __float2bfloat16(e1 - __bfloat162float(h1));
        hp[j] = (uint32_t)__bfloat16_as_ushort(h0) | ((uint32_t)__bfloat16_as_ushort(h1) << 16);
        lp[j] = (uint32_t)__bfloat16_as_ushort(l0) | ((uint32_t)__bfloat16_as_ushort(l1) << 16);
    }
    size_t base = (size_t)o * 512 + u*8;
    *(uint4*)&g_B2[base]       = make_uint4(hp[0], hp[1], hp[2], hp[3]);
    *(uint4*)&g_B2[base + 256] = make_uint4(lp[0], lp[1], lp[2], lp[3]);
}

// ---------------- bf16 mma.sync GEMM with 3-term split (effective K = 768) --
// out[m,o] = sum_k xd[m,k]*wp[o,k] + bias[o]
// CTA tile 128x128, BK=64, 8 warps (4m x 2n), double-buffered cp.async.
// K-iteration schedule: term 0: Ahi*Bhi, term 1: Ahi*Blo, term 2: Alo*Bhi.
#define GSTAGE 32768   // bytes per stage: A 16K + B 16K

__global__ void __launch_bounds__(256) k_gemm_mma(float* __restrict__ out) {
    extern __shared__ unsigned char smraw[];
    uint32_t rawb = smem_to_u32(smraw);
    uint32_t smb = (rawb + 1023) & ~1023u;   // 1024-aligned base (u32 shared addr)
    const int tid = threadIdx.x;
    const int wid = tid >> 5, lane = tid & 31;
    const int tile_n = blockIdx.x & 3, tile_m = blockIdx.x >> 2;
    const int warp_m = wid & 3, warp_n = wid >> 2;   // 4 x 2 warp grid

    const __nv_bfloat16* gA = g_A2 + (size_t)tile_m * 128 * 512;
    const __nv_bfloat16* gB = g_B2 + (size_t)tile_n * 128 * 512;

    float acc[2][8][4];
    #pragma unroll
    for (int mt = 0; mt < 2; mt++)
        #pragma unroll
        for (int nt = 0; nt < 8; nt++)
            #pragma unroll
            for (int i = 0; i < 4; i++) acc[mt][nt][i] = 0.f;

    // ---- async tile loader: iteration it -> (a_k0, b_k0), stage s ----
    auto load_tiles = [&](int it, int s) {
        int term = it >> 2, j = it & 3;
        int a_k0 = ((term == 2) ? 256 : 0) + j*64;   // bf16 elem offset in A2 row
        int b_k0 = ((term == 1) ? 256 : 0) + j*64;
        uint32_t sa = smb + s*GSTAGE;
        uint32_t sb = sa + 16384;
        #pragma unroll
        for (int i = 0; i < 4; i++) {
            int idx = tid + i*256;          // 1024 chunks of 16B
            int r = idx >> 3, kc = idx & 7; // row, 16B-chunk within 128B row
            cp16(sa + swz(r*128 + kc*16), (const char*)(gA + (size_t)r*512 + a_k0) + kc*16);
        }
        #pragma unroll
        for (int i = 0; i < 4; i++) {
            int idx = tid + i*256;
            int r = idx >> 3, kc = idx & 7;
            cp16(sb + swz(r*128 + kc*16), (const char*)(gB + (size_t)r*512 + b_k0) + kc*16);
        }
        asm volatile("cp.async.commit_group;" ::: "memory");
    };

    load_tiles(0, 0);

    for (int it = 0; it < 12; ++it) {
        int s = it & 1;
        if (it + 1 < 12) {
            load_tiles(it + 1, s ^ 1);
            asm volatile("cp.async.wait_group 1;" ::: "memory");
        } else {
            asm volatile("cp.async.wait_group 0;" ::: "memory");
        }
        __syncthreads();

        uint32_t smA = smb + s*GSTAGE;
        uint32_t smB = smA + 16384;
        #pragma unroll
        for (int kt = 0; kt < 4; kt++) {     // four k16 steps within BK=64
            uint32_t afr[2][4];
            #pragma unroll
            for (int mt = 0; mt < 2; mt++) {
                int m = warp_m*32 + mt*16 + (lane & 15);
                int kb = kt*32 + ((lane >> 4) << 4);   // byte offset: k*2
                ldmx4(afr[mt], smA + swz(m*128 + kb));
            }
            uint32_t bfr[4][4];
            #pragma unroll
            for (int np = 0; np < 4; np++) {
                int n = warp_n*64 + np*16 + (lane & 7) + ((lane >> 4) << 3);
                int kb = kt*32 + (((lane >> 3) & 1) << 4);
                ldmx4(bfr[np], smB + swz(n*128 + kb));
            }
            #pragma unroll
            for (int mt = 0; mt < 2; mt++)
                #pragma unroll
                for (int nt = 0; nt < 8; nt++)
                    mma16816(acc[mt][nt], afr[mt], &bfr[nt >> 1][(nt & 1)*2]);
        }
        __syncthreads();
    }

    // epilogue: + bias, write fp32
    #pragma unroll
    for (int mt = 0; mt < 2; mt++) {
        int row = tile_m*128 + warp_m*32 + mt*16 + (lane >> 2);
        #pragma unroll
        for (int nt = 0; nt < 8; nt++) {
            int col = tile_n*128 + warp_n*64 + nt*8 + ((lane & 3) << 1);
            float b0 = g_bias[col], b1 = g_bias[col + 1];
            float2 v0 = make_float2(acc[mt][nt][0] + b0, acc[mt][nt][1] + b1);
            float2 v1 = make_float2(acc[mt][nt][2] + b0, acc[mt][nt][3] + b1);
            *(float2*)&out[(size_t)row*COUT + col]       = v0;
            *(float2*)&out[(size_t)(row + 8)*COUT + col] = v1;
        }
    }
}

// BN2 stats over d_out rows
#define RPB2 128
__global__ void k_bn2_stats(const float* __restrict__ out) {
    int o = threadIdx.x;               // 512 threads
    int r0 = blockIdx.x * RPB2;
    float s = 0.f, s2 = 0.f;
    for (int r = r0; r < r0 + RPB2; ++r) {
        float v = out[(size_t)r*COUT + o];
        s += v; s2 += v * v;
    }
    atomicAdd(&g_stats2[o], s);
    atomicAdd(&g_stats2[COUT + o], s2);
}

__global__ void k_fold2(const float* __restrict__ g2, const float* __restrict__ b2) {
    int o = threadIdx.x;
    const float inv = 1.0f / (float)MROWS;
    float mean = g_stats2[o] * inv;
    float var  = g_stats2[COUT + o] * inv - mean * mean;
    float a = g2[o] * rsqrtf(var + 1e-5f);
    g_a2[o] = a;
    g_d2[o] = b2[o] - mean * a;
}

__global__ void k_bn2_apply(float* __restrict__ out) {
    size_t idx4 = (size_t)blockIdx.x * blockDim.x + threadIdx.x; // over M*CO/4
    int o = (int)(idx4 & (COUT/4 - 1)) * 4;
    float4 v = ((float4*)out)[idx4];
    v.x = fmaxf(0.f, v.x * g_a2[o+0] + g_d2[o+0]);
    v.y = fmaxf(0.f, v.y * g_a2[o+1] + g_d2[o+1]);
    v.z = fmaxf(0.f, v.z * g_a2[o+2] + g_d2[o+2]);
    v.w = fmaxf(0.f, v.w * g_a2[o+3] + g_d2[o+3]);
    ((float4*)out)[idx4] = v;
}

// ---------------- launch ----------------
extern "C" void kernel_launch(void* const* d_in, const int* in_sizes, int n_in,
                              void* d_out, int out_size) {
    const float* x     = (const float*)d_in[0];   // (B,N,C)
    const float* loc   = (const float*)d_in[1];   // (B,N,2)
    const int*   idxa  = (const int*)  d_in[2];   // (B,N)
    const int*   idxat = (const int*)  d_in[5];   // (B,N)
    const float* wt    = (const float*)d_in[6];   // (B,N,1)
    const float* dwc   = (const float*)d_in[9];   // (C,1,3,3)
    const float* dws   = (const float*)d_in[10];  // (C,1,1,1)
    const float* g1    = (const float*)d_in[11];
    const float* b1    = (const float*)d_in[12];
    const float* cw    = (const float*)d_in[13];  // (CO,C)
    const float* g2    = (const float*)d_in[14];
    const float* b2    = (const float*)d_in[15];
    float* out = (float*)d_out;

    const int GEMM_SMEM = 2*GSTAGE + 1024;
    cudaFuncSetAttribute(k_gemm_mma, cudaFuncAttributeMaxDynamicSharedMemorySize, GEMM_SMEM);

    k_zero<<<2048, 256>>>();
    k_scatter_map<<<BB*NN, CC>>>(x, loc, idxa);
    k_invcnt<<<(BB*HWC)/256, 256>>>();
    k_dwconv<<<BB*HW2, CC>>>(dwc);
    k_scatter_tok<<<BB*NN, CC>>>(x, loc, idxa, idxat, wt, dws);
    k_bn1_stats<<<MROWS/RPB1, CC>>>();
    k_fold<<<COUT, CC>>>(cw, g1, b1);
    k_packA<<<(MROWS*32)/256, 256>>>();
    k_packB<<<(COUT*32)/256, 256>>>();
    k_gemm_mma<<<(MROWS/128)*(COUT/128), 256, GEMM_SMEM>>>(out);
    k_bn2_stats<<<MROWS/RPB2, COUT>>>(out);
    k_fold2<<<1, COUT>>>(g2, b2);
    k_bn2_apply<<<(MROWS*COUT/4)/256, 256>>>(out);
}

// round 4
// speedup vs baseline: 2.3913x; 1.6300x over previous
#include <cuda_runtime.h>
#include <cuda_bf16.h>
#include <cstdint>

// Problem constants (fixed shapes from the reference)
#define BB   8
#define NN   12288
#define NTOK 3072
#define CC   256
#define COUT 512
#define HH   128
#define WW   96
#define HWC  (HH*WW)        // 12288 cells
#define H2   64
#define W2   48
#define HW2  (H2*W2)        // 3072 cells
#define MROWS (BB*NTOK)     // 24576

// ---------------- scratch (device globals; no allocation allowed) ----------
__device__ float g_map [(size_t)BB*HWC*CC];   // (b, cell, c) token2map sums
__device__ float g_cnt [BB*HWC];              // counts -> reciprocal counts
__device__ float g_conv[(size_t)BB*HW2*CC];   // depthwise conv output (b, cell2, c)
__device__ float g_num [(size_t)BB*NTOK*CC];  // fused numerator accumulator
__device__ float g_den [BB*NTOK];
__device__ float g_stats1[2*CC];              // sum, sumsq per C channel
__device__ float g_stats2[2*COUT];            // sum, sumsq per CO channel
__device__ float g_wp  [COUT*CC];             // BN1-folded weights
__device__ float g_bias[COUT];                // BN1-folded bias

// packed bf16 operands: A2 = [Ahi | Alo] per row (M x 512), B2 = [Bhi | Blo] (512 x 512)
__device__ __align__(16) __nv_bfloat16 g_A2[(size_t)MROWS*512];
__device__ __align__(16) __nv_bfloat16 g_B2[(size_t)COUT*512];

// ---------------- helpers ----------------
__device__ __forceinline__ uint32_t smem_to_u32(const void* p) {
    uint32_t a;
    asm("{ .reg .u64 t; cvta.to.shared.u64 t, %1; cvt.u32.u64 %0, t; }" : "=r"(a) : "l"(p));
    return a;
}
__device__ __forceinline__ int grid_cell(float lx, float ly, int h, int w) {
    lx = fminf(fmaxf(lx, -1.0f), 1.0f);
    ly = fminf(fmaxf(ly, -1.0f), 1.0f);
    float fx = __fadd_rn(__fmul_rn(__fmul_rn(0.5f, __fadd_rn(lx, 1.0f)), (float)w), -0.5f);
    float fy = __fadd_rn(__fmul_rn(__fmul_rn(0.5f, __fadd_rn(ly, 1.0f)), (float)h), -0.5f);
    int xi = __float2int_rn(fx);   // round-to-nearest-even matches jnp.round
    int yi = __float2int_rn(fy);
    xi = min(max(xi, 0), w - 1);
    yi = min(max(yi, 0), h - 1);
    return xi + yi * w;
}
// SW128 swizzle (Swizzle<3,4,3>) on within-tile byte offsets (128B rows)
__device__ __forceinline__ int swz(int byte) { return byte ^ ((byte >> 3) & 0x70); }

__device__ __forceinline__ void cp16(uint32_t s, const void* g) {
    asm volatile("cp.async.cg.shared.global [%0], [%1], 16;" :: "r"(s), "l"(g));
}
__device__ __forceinline__ void ldmx4(uint32_t* r, uint32_t addr) {
    asm volatile("ldmatrix.sync.aligned.m8n8.x4.shared.b16 {%0,%1,%2,%3}, [%4];"
        : "=r"(r[0]), "=r"(r[1]), "=r"(r[2]), "=r"(r[3]) : "r"(addr));
}
__device__ __forceinline__ void mma16816(float* c, const uint32_t* a, const uint32_t* b) {
    asm volatile("mma.sync.aligned.m16n8k16.row.col.f32.bf16.bf16.f32 "
        "{%0,%1,%2,%3}, {%4,%5,%6,%7}, {%8,%9}, {%0,%1,%2,%3};"
        : "+f"(c[0]), "+f"(c[1]), "+f"(c[2]), "+f"(c[3])
        : "r"(a[0]), "r"(a[1]), "r"(a[2]), "r"(a[3]), "r"(b[0]), "r"(b[1]));
}
// vectorized global reduction (sm_90+): 4 floats, one REDG
__device__ __forceinline__ void red4(float* addr, float4 v) {
    asm volatile("red.global.add.v4.f32 [%0], {%1,%2,%3,%4};"
        :: "l"(addr), "f"(v.x), "f"(v.y), "f"(v.z), "f"(v.w) : "memory");
}

// ---------------- kernels ----------------
__global__ void k_zero() {
    size_t i = (size_t)blockIdx.x * blockDim.x + threadIdx.x;
    size_t stride = (size_t)gridDim.x * blockDim.x;
    const float4 z = make_float4(0.f, 0.f, 0.f, 0.f);
    float4* m4 = (float4*)g_map;
    for (size_t k = i; k < (size_t)BB*HWC*CC/4; k += stride) m4[k] = z;
    float4* n4 = (float4*)g_num;
    for (size_t k = i; k < (size_t)BB*NTOK*CC/4; k += stride) n4[k] = z;
    float4* c4 = (float4*)g_cnt;
    for (size_t k = i; k < (size_t)(BB*HWC/4); k += stride) c4[k] = z;
    float4* d4 = (float4*)g_den;
    for (size_t k = i; k < (size_t)(BB*NTOK/4); k += stride) d4[k] = z;
    if (i < 2*CC)  g_stats1[i] = 0.f;
    if (i < 2*COUT) g_stats2[i] = 0.f;
}

// Pass 1: read x[src] ONCE; scatter (a) x into the map grid, (b) the skip
// term x*dw_skip*w into g_num, plus cnt/den. 64 threads x float4 per token.
__global__ void __launch_bounds__(256) k_scatter1(
        const float* __restrict__ x,
        const float* __restrict__ loc,
        const int*   __restrict__ idx_agg,
        const int*   __restrict__ idx_agg_t,
        const float* __restrict__ wgt_t,
        const float* __restrict__ dw_skip) {
    int tok = blockIdx.x * 4 + (threadIdx.x >> 6);   // b*N + i
    int q   = threadIdx.x & 63;                       // channel quad
    int b = tok / NN;
    float lx = loc[2*tok + 0], ly = loc[2*tok + 1];
    int cell = grid_cell(lx, ly, HH, WW);
    int src  = idx_agg[tok];
    int tgt  = idx_agg_t[tok];
    float w  = wgt_t[tok];
    float4 xv = *(const float4*)&x[((size_t)b*NN + src)*CC + q*4];
    red4(&g_map[((size_t)b*HWC + cell)*CC + q*4], xv);
    float4 dw = *(const float4*)&dw_skip[q*4];
    float4 sv = make_float4(xv.x*dw.x*w, xv.y*dw.y*w, xv.z*dw.z*w, xv.w*dw.w*w);
    red4(&g_num[((size_t)b*NTOK + tgt)*CC + q*4], sv);
    if (q == 0) {
        atomicAdd(&g_cnt[b*HWC + cell], 1.0f);
        atomicAdd(&g_den[b*NTOK + tgt], w);
    }
}

__global__ void k_invcnt() {
    int i = blockIdx.x * blockDim.x + threadIdx.x;
    if (i < BB*HWC) g_cnt[i] = 1.0f / (g_cnt[i] + 1e-6f);
}

// depthwise 3x3 stride-2 conv with fused count-normalization.
// 4 pixels/block, 64 threads x float4 channels; weights transposed in smem.
__global__ void __launch_bounds__(256) k_dwconv(const float* __restrict__ wc) {
    __shared__ float wsm[9*CC];
    int t = threadIdx.x;
    #pragma unroll
    for (int i = 0; i < 9; i++) {
        int idx = t + i*256;   // 2304 total
        int k = idx / CC, c = idx - k*CC;
        wsm[k*CC + c] = wc[c*9 + k];
    }
    __syncthreads();
    int pix = blockIdx.x * 4 + (t >> 6);   // b*HW2 + cell2
    int q   = (t & 63) * 4;
    int b = pix / HW2;
    int cell = pix - b * HW2;
    int y2 = cell / W2, x2 = cell - y2 * W2;
    float4 acc = make_float4(0.f, 0.f, 0.f, 0.f);
    #pragma unroll
    for (int ky = 0; ky < 3; ky++) {
        int y = 2*y2 - 1 + ky;
        if ((unsigned)y >= HH) continue;
        #pragma unroll
        for (int kx = 0; kx < 3; kx++) {
            int xx = 2*x2 - 1 + kx;
            if ((unsigned)xx >= WW) continue;
            int ci = b*HWC + y*WW + xx;
            float iv = __ldg(&g_cnt[ci]);
            float4 m = *(const float4*)&g_map[(size_t)ci*CC + q];
            const float* wk = &wsm[(ky*3 + kx)*CC + q];
            acc.x += m.x * (iv * wk[0]);
            acc.y += m.y * (iv * wk[1]);
            acc.z += m.z * (iv * wk[2]);
            acc.w += m.w * (iv * wk[3]);
        }
    }
    *(float4*)&g_conv[(size_t)pix*CC + q] = acc;
}

// Pass 2: scatter the conv feature term feat*w into g_num (conv is L2-resident)
__global__ void __launch_bounds__(256) k_scatter2(
        const float* __restrict__ loc,
        const int*   __restrict__ idx_agg_t,
        const float* __restrict__ wgt_t) {
    int tok = blockIdx.x * 4 + (threadIdx.x >> 6);
    int q   = threadIdx.x & 63;
    int b = tok / NN;
    float lx = loc[2*tok + 0], ly = loc[2*tok + 1];
    int cell2 = grid_cell(lx, ly, H2, W2);
    int tgt   = idx_agg_t[tok];
    float w   = wgt_t[tok];
    float4 f = *(const float4*)&g_conv[((size_t)b*HW2 + cell2)*CC + q*4];
    f.x *= w; f.y *= w; f.z *= w; f.w *= w;
    red4(&g_num[((size_t)b*NTOK + tgt)*CC + q*4], f);
}

// BN1 per-channel stats of xd = num/(den+eps) (no materialization)
#define RPB1 96
__global__ void k_bn1_stats() {
    int c = threadIdx.x;
    int r0 = blockIdx.x * RPB1;
    float s = 0.f, s2 = 0.f;
    for (int r = r0; r < r0 + RPB1; ++r) {
        float rden = 1.0f / (g_den[r] + 1e-6f);
        float v = g_num[(size_t)r*CC + c] * rden;
        s += v; s2 += v * v;
    }
    atomicAdd(&g_stats1[c], s);
    atomicAdd(&g_stats1[CC + c], s2);
}

// fold BN1 into the 1x1 conv: W'[o,c] = W[o,c]*a_c ; bias'[o] = sum_c d_c*W[o,c]
__global__ void k_fold(const float* __restrict__ conv_w,
                       const float* __restrict__ g1,
                       const float* __restrict__ b1) {
    __shared__ float red[CC];
    int o = blockIdx.x, c = threadIdx.x;
    const float inv = 1.0f / (float)MROWS;
    float mean = g_stats1[c] * inv;
    float var  = g_stats1[CC + c] * inv - mean * mean;
    float a = g1[c] * rsqrtf(var + 1e-5f);
    float d = b1[c] - mean * a;
    float w = conv_w[o*CC + c];
    g_wp[o*CC + c] = w * a;
    red[c] = d * w;
    __syncthreads();
    for (int s = CC/2; s > 0; s >>= 1) {
        if (c < s) red[c] += red[c + s];
        __syncthreads();
    }
    if (c == 0) g_bias[o] = red[0];
}

// pack A2 = [bf16_hi(xd) | bf16_lo(xd)] row-major M x 512
__global__ void k_packA() {
    int idx = blockIdx.x * 256 + threadIdx.x;   // MROWS*32
    int m = idx >> 5, u = idx & 31;
    float rden = 1.0f / (g_den[m] + 1e-6f);
    const float4* src = (const float4*)&g_num[(size_t)m*CC + u*8];
    float4 v0 = src[0], v1 = src[1];
    float vv[8] = {v0.x, v0.y, v0.z, v0.w, v1.x, v1.y, v1.z, v1.w};
    uint32_t hp[4], lp[4];
    #pragma unroll
    for (int j = 0; j < 4; j++) {
        float e0 = vv[2*j] * rden, e1 = vv[2*j+1] * rden;
        __nv_bfloat16 h0 = __float2bfloat16(e0), h1 = __float2bfloat16(e1);
        __nv_bfloat16 l0 = __float2bfloat16(e0 - __bfloat162float(h0));
        __nv_bfloat16 l1 = __float2bfloat16(e1 - __bfloat162float(h1));
        hp[j] = (uint32_t)__bfloat16_as_ushort(h0) | ((uint32_t)__bfloat16_as_ushort(h1) << 16);
        lp[j] = (uint32_t)__bfloat16_as_ushort(l0) | ((uint32_t)__bfloat16_as_ushort(l1) << 16);
    }
    size_t base = (size_t)m * 512 + u*8;
    *(uint4*)&g_A2[base]       = make_uint4(hp[0], hp[1], hp[2], hp[3]);
    *(uint4*)&g_A2[base + 256] = make_uint4(lp[0], lp[1], lp[2], lp[3]);
}

// pack B2 = [bf16_hi(wp) | bf16_lo(wp)] row-major CO x 512
__global__ void k_packB() {
    int idx = blockIdx.x * 256 + threadIdx.x;   // COUT*32
    int o = idx >> 5, u = idx & 31;
    const float4* src = (const float4*)&g_wp[(size_t)o*CC + u*8];
    float4 v0 = src[0], v1 = src[1];
    float vv[8] = {v0.x, v0.y, v0.z, v0.w, v1.x, v1.y, v1.z, v1.w};
    uint32_t hp[4], lp[4];
    #pragma unroll
    for (int j = 0; j < 4; j++) {
        float e0 = vv[2*j], e1 = vv[2*j+1];
        __nv_bfloat16 h0 = __float2bfloat16(e0), h1 = __float2bfloat16(e1);
        __nv_bfloat16 l0 = __float2bfloat16(e0 - __bfloat162float(h0));
        __nv_bfloat16 l1 = __float2bfloat16(e1 - __bfloat162float(h1));
        hp[j] = (uint32_t)__bfloat16_as_ushort(h0) | ((uint32_t)__bfloat16_as_ushort(h1) << 16);
        lp[j] = (uint32_t)__bfloat16_as_ushort(l0) | ((uint32_t)__bfloat16_as_ushort(l1) << 16);
    }
    size_t base = (size_t)o * 512 + u*8;
    *(uint4*)&g_B2[base]       = make_uint4(hp[0], hp[1], hp[2], hp[3]);
    *(uint4*)&g_B2[base + 256] = make_uint4(lp[0], lp[1], lp[2], lp[3]);
}

// ---------------- bf16 mma.sync GEMM with 3-term split (effective K = 768) --
#define GSTAGE 32768   // bytes per stage: A 16K + B 16K

__global__ void __launch_bounds__(256) k_gemm_mma(float* __restrict__ out) {
    extern __shared__ unsigned char smraw[];
    uint32_t rawb = smem_to_u32(smraw);
    uint32_t smb = (rawb + 1023) & ~1023u;
    const int tid = threadIdx.x;
    const int wid = tid >> 5, lane = tid & 31;
    const int tile_n = blockIdx.x & 3, tile_m = blockIdx.x >> 2;
    const int warp_m = wid & 3, warp_n = wid >> 2;   // 4 x 2 warp grid

    const __nv_bfloat16* gA = g_A2 + (size_t)tile_m * 128 * 512;
    const __nv_bfloat16* gB = g_B2 + (size_t)tile_n * 128 * 512;

    float acc[2][8][4];
    #pragma unroll
    for (int mt = 0; mt < 2; mt++)
        #pragma unroll
        for (int nt = 0; nt < 8; nt++)
            #pragma unroll
            for (int i = 0; i < 4; i++) acc[mt][nt][i] = 0.f;

    auto load_tiles = [&](int it, int s) {
        int term = it >> 2, j = it & 3;
        int a_k0 = ((term == 2) ? 256 : 0) + j*64;
        int b_k0 = ((term == 1) ? 256 : 0) + j*64;
        uint32_t sa = smb + s*GSTAGE;
        uint32_t sb = sa + 16384;
        #pragma unroll
        for (int i = 0; i < 4; i++) {
            int idx = tid + i*256;
            int r = idx >> 3, kc = idx & 7;
            cp16(sa + swz(r*128 + kc*16), (const char*)(gA + (size_t)r*512 + a_k0) + kc*16);
        }
        #pragma unroll
        for (int i = 0; i < 4; i++) {
            int idx = tid + i*256;
            int r = idx >> 3, kc = idx & 7;
            cp16(sb + swz(r*128 + kc*16), (const char*)(gB + (size_t)r*512 + b_k0) + kc*16);
        }
        asm volatile("cp.async.commit_group;" ::: "memory");
    };

    load_tiles(0, 0);

    for (int it = 0; it < 12; ++it) {
        int s = it & 1;
        if (it + 1 < 12) {
            load_tiles(it + 1, s ^ 1);
            asm volatile("cp.async.wait_group 1;" ::: "memory");
        } else {
            asm volatile("cp.async.wait_group 0;" ::: "memory");
        }
        __syncthreads();

        uint32_t smA = smb + s*GSTAGE;
        uint32_t smB = smA + 16384;
        #pragma unroll
        for (int kt = 0; kt < 4; kt++) {
            uint32_t afr[2][4];
            #pragma unroll
            for (int mt = 0; mt < 2; mt++) {
                int m = warp_m*32 + mt*16 + (lane & 15);
                int kb = kt*32 + ((lane >> 4) << 4);
                ldmx4(afr[mt], smA + swz(m*128 + kb));
            }
            uint32_t bfr[4][4];
            #pragma unroll
            for (int np = 0; np < 4; np++) {
                int n = warp_n*64 + np*16 + (lane & 7) + ((lane >> 4) << 3);
                int kb = kt*32 + (((lane >> 3) & 1) << 4);
                ldmx4(bfr[np], smB + swz(n*128 + kb));
            }
            #pragma unroll
            for (int mt = 0; mt < 2; mt++)
                #pragma unroll
                for (int nt = 0; nt < 8; nt++)
                    mma16816(acc[mt][nt], afr[mt], &bfr[nt >> 1][(nt & 1)*2]);
        }
        __syncthreads();
    }

    #pragma unroll
    for (int mt = 0; mt < 2; mt++) {
        int row = tile_m*128 + warp_m*32 + mt*16 + (lane >> 2);
        #pragma unroll
        for (int nt = 0; nt < 8; nt++) {
            int col = tile_n*128 + warp_n*64 + nt*8 + ((lane & 3) << 1);
            float b0 = g_bias[col], b1 = g_bias[col + 1];
            float2 v0 = make_float2(acc[mt][nt][0] + b0, acc[mt][nt][1] + b1);
            float2 v1 = make_float2(acc[mt][nt][2] + b0, acc[mt][nt][3] + b1);
            *(float2*)&out[(size_t)row*COUT + col]       = v0;
            *(float2*)&out[(size_t)(row + 8)*COUT + col] = v1;
        }
    }
}

// BN2 stats over d_out rows
#define RPB2 128
__global__ void k_bn2_stats(const float* __restrict__ out) {
    int o = threadIdx.x;               // 512 threads
    int r0 = blockIdx.x * RPB2;
    float s = 0.f, s2 = 0.f;
    for (int r = r0; r < r0 + RPB2; ++r) {
        float v = out[(size_t)r*COUT + o];
        s += v; s2 += v * v;
    }
    atomicAdd(&g_stats2[o], s);
    atomicAdd(&g_stats2[COUT + o], s2);
}

// BN2 fold + apply + relu fused (per-block recompute of scale/shift)
__global__ void __launch_bounds__(256) k_bn2_apply(float* __restrict__ out,
                                                   const float* __restrict__ g2,
                                                   const float* __restrict__ b2) {
    __shared__ float sa[COUT], sd[COUT];
    int t = threadIdx.x;
    const float inv = 1.0f / (float)MROWS;
    #pragma unroll
    for (int i = t; i < COUT; i += 256) {
        float mean = g_stats2[i] * inv;
        float var  = g_stats2[COUT + i] * inv - mean * mean;
        float a = g2[i] * rsqrtf(var + 1e-5f);
        sa[i] = a;
        sd[i] = b2[i] - mean * a;
    }
    __syncthreads();
    // 2048 blocks x 256 threads x 6 float4 = M*CO
    #pragma unroll
    for (int it = 0; it < 6; it++) {
        size_t idx4 = (size_t)blockIdx.x * 256 + t + (size_t)it * 524288;
        int o = (int)(idx4 & (COUT/4 - 1)) * 4;
        float4 v = ((float4*)out)[idx4];
        v.x = fmaxf(0.f, v.x * sa[o+0] + sd[o+0]);
        v.y = fmaxf(0.f, v.y * sa[o+1] + sd[o+1]);
        v.z = fmaxf(0.f, v.z * sa[o+2] + sd[o+2]);
        v.w = fmaxf(0.f, v.w * sa[o+3] + sd[o+3]);
        ((float4*)out)[idx4] = v;
    }
}

// ---------------- launch ----------------
extern "C" void kernel_launch(void* const* d_in, const int* in_sizes, int n_in,
                              void* d_out, int out_size) {
    const float* x     = (const float*)d_in[0];   // (B,N,C)
    const float* loc   = (const float*)d_in[1];   // (B,N,2)
    const int*   idxa  = (const int*)  d_in[2];   // (B,N)
    const int*   idxat = (const int*)  d_in[5];   // (B,N)
    const float* wt    = (const float*)d_in[6];   // (B,N,1)
    const float* dwc   = (const float*)d_in[9];   // (C,1,3,3)
    const float* dws   = (const float*)d_in[10];  // (C,1,1,1)
    const float* g1    = (const float*)d_in[11];
    const float* b1    = (const float*)d_in[12];
    const float* cw    = (const float*)d_in[13];  // (CO,C)
    const float* g2    = (const float*)d_in[14];
    const float* b2    = (const float*)d_in[15];
    float* out = (float*)d_out;

    const int GEMM_SMEM = 2*GSTAGE + 1024;
    cudaFuncSetAttribute(k_gemm_mma, cudaFuncAttributeMaxDynamicSharedMemorySize, GEMM_SMEM);

    k_zero<<<2048, 256>>>();
    k_scatter1<<<BB*NN/4, 256>>>(x, loc, idxa, idxat, wt, dws);
    k_invcnt<<<(BB*HWC)/256, 256>>>();
    k_dwconv<<<BB*HW2/4, 256>>>(dwc);
    k_scatter2<<<BB*NN/4, 256>>>(loc, idxat, wt);
    k_bn1_stats<<<MROWS/RPB1, CC>>>();
    k_fold<<<COUT, CC>>>(cw, g1, b1);
    k_packA<<<(MROWS*32)/256, 256>>>();
    k_packB<<<(COUT*32)/256, 256>>>();
    k_gemm_mma<<<(MROWS/128)*(COUT/128), 256, GEMM_SMEM>>>(out);
    k_bn2_stats<<<MROWS/RPB2, COUT>>>(out);
    k_bn2_apply<<<2048, 256>>>(out, g2, b2);
}

// round 5
// speedup vs baseline: 2.5973x; 1.0861x over previous
#include <cuda_runtime.h>
#include <cuda_bf16.h>
#include <cstdint>

// Problem constants (fixed shapes from the reference)
#define BB   8
#define NN   12288
#define NTOK 3072
#define CC   256
#define COUT 512
#define HH   128
#define WW   96
#define HWC  (HH*WW)        // 12288 cells
#define H2   64
#define W2   48
#define HW2  (H2*W2)        // 3072 cells
#define MROWS (BB*NTOK)     // 24576

// ---------------- scratch (device globals; no allocation allowed) ----------
__device__ float g_map [(size_t)BB*HWC*CC];   // (b, cell, c) token2map sums
__device__ float g_cnt [BB*HWC];              // counts -> reciprocal counts
__device__ float g_conv[(size_t)BB*HW2*CC];   // depthwise conv output (b, cell2, c)
__device__ float g_num [(size_t)BB*NTOK*CC];  // fused numerator accumulator
__device__ float g_den [BB*NTOK];
__device__ float g_stats1[2*CC];              // sum, sumsq per C channel
__device__ float g_stats2[2*COUT];            // sum, sumsq per CO channel
__device__ float g_bias[COUT];                // BN1-folded bias

// packed bf16 operands: A2 = [Ahi | Alo] per row (M x 512), B2 = [Bhi | Blo] (512 x 512)
__device__ __align__(16) __nv_bfloat16 g_A2[(size_t)MROWS*512];
__device__ __align__(16) __nv_bfloat16 g_B2[(size_t)COUT*512];

// ---------------- helpers ----------------
__device__ __forceinline__ uint32_t smem_to_u32(const void* p) {
    uint32_t a;
    asm("{ .reg .u64 t; cvta.to.shared.u64 t, %1; cvt.u32.u64 %0, t; }" : "=r"(a) : "l"(p));
    return a;
}
__device__ __forceinline__ int grid_cell(float lx, float ly, int h, int w) {
    lx = fminf(fmaxf(lx, -1.0f), 1.0f);
    ly = fminf(fmaxf(ly, -1.0f), 1.0f);
    float fx = __fadd_rn(__fmul_rn(__fmul_rn(0.5f, __fadd_rn(lx, 1.0f)), (float)w), -0.5f);
    float fy = __fadd_rn(__fmul_rn(__fmul_rn(0.5f, __fadd_rn(ly, 1.0f)), (float)h), -0.5f);
    int xi = __float2int_rn(fx);   // round-to-nearest-even matches jnp.round
    int yi = __float2int_rn(fy);
    xi = min(max(xi, 0), w - 1);
    yi = min(max(yi, 0), h - 1);
    return xi + yi * w;
}
// SW128 swizzle (Swizzle<3,4,3>) on within-tile byte offsets (128B rows)
__device__ __forceinline__ int swz(int byte) { return byte ^ ((byte >> 3) & 0x70); }

__device__ __forceinline__ void cp16(uint32_t s, const void* g) {
    asm volatile("cp.async.cg.shared.global [%0], [%1], 16;" :: "r"(s), "l"(g));
}
__device__ __forceinline__ void ldmx4(uint32_t* r, uint32_t addr) {
    asm volatile("ldmatrix.sync.aligned.m8n8.x4.shared.b16 {%0,%1,%2,%3}, [%4];"
        : "=r"(r[0]), "=r"(r[1]), "=r"(r[2]), "=r"(r[3]) : "r"(addr));
}
__device__ __forceinline__ void mma16816(float* c, const uint32_t* a, const uint32_t* b) {
    asm volatile("mma.sync.aligned.m16n8k16.row.col.f32.bf16.bf16.f32 "
        "{%0,%1,%2,%3}, {%4,%5,%6,%7}, {%8,%9}, {%0,%1,%2,%3};"
        : "+f"(c[0]), "+f"(c[1]), "+f"(c[2]), "+f"(c[3])
        : "r"(a[0]), "r"(a[1]), "r"(a[2]), "r"(a[3]), "r"(b[0]), "r"(b[1]));
}
// vectorized global reduction (sm_90+): 4 floats, one REDG
__device__ __forceinline__ void red4(float* addr, float4 v) {
    asm volatile("red.global.add.v4.f32 [%0], {%1,%2,%3,%4};"
        :: "l"(addr), "f"(v.x), "f"(v.y), "f"(v.z), "f"(v.w) : "memory");
}
__device__ __forceinline__ uint32_t pack2bf(float a, float b) {
    __nv_bfloat16 x = __float2bfloat16(a), y = __float2bfloat16(b);
    return (uint32_t)__bfloat16_as_ushort(x) | ((uint32_t)__bfloat16_as_ushort(y) << 16);
}

// ---------------- kernels ----------------
__global__ void k_zero() {
    size_t i = (size_t)blockIdx.x * blockDim.x + threadIdx.x;
    size_t stride = (size_t)gridDim.x * blockDim.x;
    const float4 z = make_float4(0.f, 0.f, 0.f, 0.f);
    float4* m4 = (float4*)g_map;
    for (size_t k = i; k < (size_t)BB*HWC*CC/4; k += stride) m4[k] = z;
    float4* n4 = (float4*)g_num;
    for (size_t k = i; k < (size_t)BB*NTOK*CC/4; k += stride) n4[k] = z;
    float4* c4 = (float4*)g_cnt;
    for (size_t k = i; k < (size_t)(BB*HWC/4); k += stride) c4[k] = z;
    float4* d4 = (float4*)g_den;
    for (size_t k = i; k < (size_t)(BB*NTOK/4); k += stride) d4[k] = z;
    if (i < 2*CC)  g_stats1[i] = 0.f;
    if (i < 2*COUT) g_stats2[i] = 0.f;
}

// Pass 1: read x[src] ONCE; scatter (a) x into the map grid, (b) the skip
// term x*dw_skip*w into g_num, plus cnt/den. 64 threads x float4 per token.
__global__ void __launch_bounds__(256) k_scatter1(
        const float* __restrict__ x,
        const float* __restrict__ loc,
        const int*   __restrict__ idx_agg,
        const int*   __restrict__ idx_agg_t,
        const float* __restrict__ wgt_t,
        const float* __restrict__ dw_skip) {
    int tok = blockIdx.x * 4 + (threadIdx.x >> 6);   // b*N + i
    int q   = threadIdx.x & 63;                       // channel quad
    int b = tok / NN;
    float lx = loc[2*tok + 0], ly = loc[2*tok + 1];
    int cell = grid_cell(lx, ly, HH, WW);
    int src  = idx_agg[tok];
    int tgt  = idx_agg_t[tok];
    float w  = wgt_t[tok];
    float4 xv = *(const float4*)&x[((size_t)b*NN + src)*CC + q*4];
    red4(&g_map[((size_t)b*HWC + cell)*CC + q*4], xv);
    float4 dw = *(const float4*)&dw_skip[q*4];
    float4 sv = make_float4(xv.x*dw.x*w, xv.y*dw.y*w, xv.z*dw.z*w, xv.w*dw.w*w);
    red4(&g_num[((size_t)b*NTOK + tgt)*CC + q*4], sv);
    if (q == 0) {
        atomicAdd(&g_cnt[b*HWC + cell], 1.0f);
        atomicAdd(&g_den[b*NTOK + tgt], w);
    }
}

__global__ void k_invcnt() {
    int i = blockIdx.x * blockDim.x + threadIdx.x;
    if (i < BB*HWC) g_cnt[i] = 1.0f / (g_cnt[i] + 1e-6f);
}

// depthwise 3x3 stride-2 conv with fused count-normalization.
// 64-thread group computes 2 adjacent output pixels (shared tap column);
// 4 groups per block -> 8 pixels/block.
__global__ void __launch_bounds__(256) k_dwconv(const float* __restrict__ wc) {
    __shared__ float wsm[9*CC];
    int t = threadIdx.x;
    #pragma unroll
    for (int i = 0; i < 9; i++) {
        int idx = t + i*256;   // 2304 total
        int k = idx / CC, c = idx - k*CC;
        wsm[k*CC + c] = wc[c*9 + k];
    }
    __syncthreads();
    int pairp = blockIdx.x * 4 + (t >> 6);   // pair index over b*HW2/2
    int q = (t & 63) * 4;
    int b = pairp / (HW2/2);
    int cp = pairp - b * (HW2/2);
    int y2 = cp / (W2/2);
    int xp = (cp - y2 * (W2/2)) * 2;         // even output x; pixels xp, xp+1
    float4 a0 = make_float4(0.f,0.f,0.f,0.f);
    float4 a1 = make_float4(0.f,0.f,0.f,0.f);
    #pragma unroll
    for (int ky = 0; ky < 3; ky++) {
        int y = 2*y2 - 1 + ky;
        if ((unsigned)y >= HH) continue;
        float4 mm[5];
        #pragma unroll
        for (int j = 0; j < 5; j++) {        // cols 2*xp-1 .. 2*xp+3
            int xx = 2*xp - 1 + j;
            if ((unsigned)xx < WW) {
                int ci = b*HWC + y*WW + xx;
                float iv = __ldg(&g_cnt[ci]);
                float4 m = *(const float4*)&g_map[(size_t)ci*CC + q];
                mm[j] = make_float4(m.x*iv, m.y*iv, m.z*iv, m.w*iv);
            } else {
                mm[j] = make_float4(0.f,0.f,0.f,0.f);
            }
        }
        #pragma unroll
        for (int kx = 0; kx < 3; kx++) {
            float4 w4 = *(const float4*)&wsm[(ky*3 + kx)*CC + q];
            a0.x += mm[kx].x*w4.x;   a0.y += mm[kx].y*w4.y;
            a0.z += mm[kx].z*w4.z;   a0.w += mm[kx].w*w4.w;
            a1.x += mm[kx+2].x*w4.x; a1.y += mm[kx+2].y*w4.y;
            a1.z += mm[kx+2].z*w4.z; a1.w += mm[kx+2].w*w4.w;
        }
    }
    size_t pix0 = (size_t)b*HW2 + y2*W2 + xp;
    *(float4*)&g_conv[pix0*CC + q]       = a0;
    *(float4*)&g_conv[(pix0 + 1)*CC + q] = a1;
}

// Pass 2: scatter the conv feature term feat*w into g_num (conv is L2-resident)
__global__ void __launch_bounds__(256) k_scatter2(
        const float* __restrict__ loc,
        const int*   __restrict__ idx_agg_t,
        const float* __restrict__ wgt_t) {
    int tok = blockIdx.x * 4 + (threadIdx.x >> 6);
    int q   = threadIdx.x & 63;
    int b = tok / NN;
    float lx = loc[2*tok + 0], ly = loc[2*tok + 1];
    int cell2 = grid_cell(lx, ly, H2, W2);
    int tgt   = idx_agg_t[tok];
    float w   = wgt_t[tok];
    float4 f = *(const float4*)&g_conv[((size_t)b*HW2 + cell2)*CC + q*4];
    f.x *= w; f.y *= w; f.z *= w; f.w *= w;
    red4(&g_num[((size_t)b*NTOK + tgt)*CC + q*4], f);
}

// Fused BN1 stats + A2 pack: one pass over g_num.
// Block: 256 threads = 4 row-lanes x 64 channel-quads; 64 rows/block.
__global__ void __launch_bounds__(256) k_bn1pack() {
    int t = threadIdx.x;
    int rr = t >> 6;          // 0..3
    int g  = t & 63;          // channel quad
    int r0 = blockIdx.x * 64;
    float s[4]  = {0.f,0.f,0.f,0.f};
    float s2[4] = {0.f,0.f,0.f,0.f};
    #pragma unroll 4
    for (int i = 0; i < 16; i++) {
        int r = r0 + i*4 + rr;
        float rden = 1.0f / (g_den[r] + 1e-6f);
        float4 v = *(const float4*)&g_num[(size_t)r*CC + g*4];
        v.x *= rden; v.y *= rden; v.z *= rden; v.w *= rden;
        // pack hi/lo bf16
        __nv_bfloat16 h0 = __float2bfloat16(v.x), h1 = __float2bfloat16(v.y);
        __nv_bfloat16 h2 = __float2bfloat16(v.z), h3 = __float2bfloat16(v.w);
        uint2 hi, lo;
        hi.x = (uint32_t)__bfloat16_as_ushort(h0) | ((uint32_t)__bfloat16_as_ushort(h1) << 16);
        hi.y = (uint32_t)__bfloat16_as_ushort(h2) | ((uint32_t)__bfloat16_as_ushort(h3) << 16);
        lo.x = pack2bf(v.x - __bfloat162float(h0), v.y - __bfloat162float(h1));
        lo.y = pack2bf(v.z - __bfloat162float(h2), v.w - __bfloat162float(h3));
        *(uint2*)&g_A2[(size_t)r*512 + g*4]       = hi;
        *(uint2*)&g_A2[(size_t)r*512 + 256 + g*4] = lo;
        s[0] += v.x; s[1] += v.y; s[2] += v.z; s[3] += v.w;
        s2[0] += v.x*v.x; s2[1] += v.y*v.y; s2[2] += v.z*v.z; s2[3] += v.w*v.w;
    }
    __shared__ float sred[4*CC], s2red[4*CC];
    #pragma unroll
    for (int j = 0; j < 4; j++) {
        sred[rr*CC + g*4 + j]  = s[j];
        s2red[rr*CC + g*4 + j] = s2[j];
    }
    __syncthreads();
    if (rr == 0) {
        #pragma unroll
        for (int j = 0; j < 4; j++) {
            int c = g*4 + j;
            float ts  = sred[c] + sred[CC + c] + sred[2*CC + c] + sred[3*CC + c];
            float ts2 = s2red[c] + s2red[CC + c] + s2red[2*CC + c] + s2red[3*CC + c];
            atomicAdd(&g_stats1[c], ts);
            atomicAdd(&g_stats1[CC + c], ts2);
        }
    }
}

// Fused: fold BN1 into 1x1 conv weights AND pack B2 hi/lo; also bias reduction.
__global__ void k_foldpack(const float* __restrict__ conv_w,
                           const float* __restrict__ g1,
                           const float* __restrict__ b1) {
    __shared__ float red[CC];
    int o = blockIdx.x, c = threadIdx.x;
    const float inv = 1.0f / (float)MROWS;
    float mean = g_stats1[c] * inv;
    float var  = g_stats1[CC + c] * inv - mean * mean;
    float a = g1[c] * rsqrtf(var + 1e-5f);
    float d = b1[c] - mean * a;
    float w = conv_w[o*CC + c];
    float wp = w * a;
    __nv_bfloat16 h = __float2bfloat16(wp);
    __nv_bfloat16 l = __float2bfloat16(wp - __bfloat162float(h));
    g_B2[(size_t)o*512 + c]       = h;
    g_B2[(size_t)o*512 + 256 + c] = l;
    red[c] = d * w;
    __syncthreads();
    for (int s = CC/2; s > 0; s >>= 1) {
        if (c < s) red[c] += red[c + s];
        __syncthreads();
    }
    if (c == 0) g_bias[o] = red[0];
}

// ---------------- bf16 mma.sync GEMM with 3-term split (effective K = 768) --
// Epilogue fuses BN2 statistics (sum, sumsq per output channel).
#define GSTAGE 32768   // bytes per stage: A 16K + B 16K

__global__ void __launch_bounds__(256) k_gemm_mma(float* __restrict__ out) {
    extern __shared__ unsigned char smraw[];
    uint32_t rawb = smem_to_u32(smraw);
    uint32_t smb = (rawb + 1023) & ~1023u;
    const int tid = threadIdx.x;
    const int wid = tid >> 5, lane = tid & 31;
    const int tile_n = blockIdx.x & 3, tile_m = blockIdx.x >> 2;
    const int warp_m = wid & 3, warp_n = wid >> 2;   // 4 x 2 warp grid

    const __nv_bfloat16* gA = g_A2 + (size_t)tile_m * 128 * 512;
    const __nv_bfloat16* gB = g_B2 + (size_t)tile_n * 128 * 512;

    float acc[2][8][4];
    #pragma unroll
    for (int mt = 0; mt < 2; mt++)
        #pragma unroll
        for (int nt = 0; nt < 8; nt++)
            #pragma unroll
            for (int i = 0; i < 4; i++) acc[mt][nt][i] = 0.f;

    auto load_tiles = [&](int it, int s) {
        int term = it >> 2, j = it & 3;
        int a_k0 = ((term == 2) ? 256 : 0) + j*64;
        int b_k0 = ((term == 1) ? 256 : 0) + j*64;
        uint32_t sa = smb + s*GSTAGE;
        uint32_t sb = sa + 16384;
        #pragma unroll
        for (int i = 0; i < 4; i++) {
            int idx = tid + i*256;
            int r = idx >> 3, kc = idx & 7;
            cp16(sa + swz(r*128 + kc*16), (const char*)(gA + (size_t)r*512 + a_k0) + kc*16);
        }
        #pragma unroll
        for (int i = 0; i < 4; i++) {
            int idx = tid + i*256;
            int r = idx >> 3, kc = idx & 7;
            cp16(sb + swz(r*128 + kc*16), (const char*)(gB + (size_t)r*512 + b_k0) + kc*16);
        }
        asm volatile("cp.async.commit_group;" ::: "memory");
    };

    load_tiles(0, 0);

    for (int it = 0; it < 12; ++it) {
        int s = it & 1;
        if (it + 1 < 12) {
            load_tiles(it + 1, s ^ 1);
            asm volatile("cp.async.wait_group 1;" ::: "memory");
        } else {
            asm volatile("cp.async.wait_group 0;" ::: "memory");
        }
        __syncthreads();

        uint32_t smA = smb + s*GSTAGE;
        uint32_t smB = smA + 16384;
        #pragma unroll
        for (int kt = 0; kt < 4; kt++) {
            uint32_t afr[2][4];
            #pragma unroll
            for (int mt = 0; mt < 2; mt++) {
                int m = warp_m*32 + mt*16 + (lane & 15);
                int kb = kt*32 + ((lane >> 4) << 4);
                ldmx4(afr[mt], smA + swz(m*128 + kb));
            }
            uint32_t bfr[4][4];
            #pragma unroll
            for (int np = 0; np < 4; np++) {
                int n = warp_n*64 + np*16 + (lane & 7) + ((lane >> 4) << 3);
                int kb = kt*32 + (((lane >> 3) & 1) << 4);
                ldmx4(bfr[np], smB + swz(n*128 + kb));
            }
            #pragma unroll
            for (int mt = 0; mt < 2; mt++)
                #pragma unroll
                for (int nt = 0; nt < 8; nt++)
                    mma16816(acc[mt][nt], afr[mt], &bfr[nt >> 1][(nt & 1)*2]);
        }
        __syncthreads();
    }

    // epilogue: + bias, write fp32, accumulate BN2 per-channel stats
    float sc[8][2], sc2[8][2];
    #pragma unroll
    for (int nt = 0; nt < 8; nt++)
        #pragma unroll
        for (int j = 0; j < 2; j++) { sc[nt][j] = 0.f; sc2[nt][j] = 0.f; }

    #pragma unroll
    for (int mt = 0; mt < 2; mt++) {
        int row = tile_m*128 + warp_m*32 + mt*16 + (lane >> 2);
        #pragma unroll
        for (int nt = 0; nt < 8; nt++) {
            int col = tile_n*128 + warp_n*64 + nt*8 + ((lane & 3) << 1);
            float b0 = g_bias[col], b1 = g_bias[col + 1];
            float2 v0 = make_float2(acc[mt][nt][0] + b0, acc[mt][nt][1] + b1);
            float2 v1 = make_float2(acc[mt][nt][2] + b0, acc[mt][nt][3] + b1);
            *(float2*)&out[(size_t)row*COUT + col]       = v0;
            *(float2*)&out[(size_t)(row + 8)*COUT + col] = v1;
            sc[nt][0]  += v0.x + v1.x;           sc[nt][1]  += v0.y + v1.y;
            sc2[nt][0] += v0.x*v0.x + v1.x*v1.x; sc2[nt][1] += v0.y*v0.y + v1.y*v1.y;
        }
    }
    // reduce over the 8 row-groups (lane>>2) via butterfly shuffles
    #pragma unroll
    for (int off = 4; off < 32; off <<= 1) {
        #pragma unroll
        for (int nt = 0; nt < 8; nt++)
            #pragma unroll
            for (int j = 0; j < 2; j++) {
                sc[nt][j]  += __shfl_xor_sync(0xffffffffu, sc[nt][j],  off);
                sc2[nt][j] += __shfl_xor_sync(0xffffffffu, sc2[nt][j], off);
            }
    }
    if (lane < 4) {
        #pragma unroll
        for (int nt = 0; nt < 8; nt++)
            #pragma unroll
            for (int j = 0; j < 2; j++) {
                int col = tile_n*128 + warp_n*64 + nt*8 + lane*2 + j;
                atomicAdd(&g_stats2[col], sc[nt][j]);
                atomicAdd(&g_stats2[COUT + col], sc2[nt][j]);
            }
    }
}

// BN2 fold + apply + relu fused (per-block recompute of scale/shift)
__global__ void __launch_bounds__(256) k_bn2_apply(float* __restrict__ out,
                                                   const float* __restrict__ g2,
                                                   const float* __restrict__ b2) {
    __shared__ float sa[COUT], sd[COUT];
    int t = threadIdx.x;
    const float inv = 1.0f / (float)MROWS;
    #pragma unroll
    for (int i = t; i < COUT; i += 256) {
        float mean = g_stats2[i] * inv;
        float var  = g_stats2[COUT + i] * inv - mean * mean;
        float a = g2[i] * rsqrtf(var + 1e-5f);
        sa[i] = a;
        sd[i] = b2[i] - mean * a;
    }
    __syncthreads();
    #pragma unroll
    for (int it = 0; it < 6; it++) {
        size_t idx4 = (size_t)blockIdx.x * 256 + t + (size_t)it * 524288;
        int o = (int)(idx4 & (COUT/4 - 1)) * 4;
        float4 v = ((float4*)out)[idx4];
        v.x = fmaxf(0.f, v.x * sa[o+0] + sd[o+0]);
        v.y = fmaxf(0.f, v.y * sa[o+1] + sd[o+1]);
        v.z = fmaxf(0.f, v.z * sa[o+2] + sd[o+2]);
        v.w = fmaxf(0.f, v.w * sa[o+3] + sd[o+3]);
        ((float4*)out)[idx4] = v;
    }
}

// ---------------- launch ----------------
extern "C" void kernel_launch(void* const* d_in, const int* in_sizes, int n_in,
                              void* d_out, int out_size) {
    const float* x     = (const float*)d_in[0];   // (B,N,C)
    const float* loc   = (const float*)d_in[1];   // (B,N,2)
    const int*   idxa  = (const int*)  d_in[2];   // (B,N)
    const int*   idxat = (const int*)  d_in[5];   // (B,N)
    const float* wt    = (const float*)d_in[6];   // (B,N,1)
    const float* dwc   = (const float*)d_in[9];   // (C,1,3,3)
    const float* dws   = (const float*)d_in[10];  // (C,1,1,1)
    const float* g1    = (const float*)d_in[11];
    const float* b1    = (const float*)d_in[12];
    const float* cw    = (const float*)d_in[13];  // (CO,C)
    const float* g2    = (const float*)d_in[14];
    const float* b2    = (const float*)d_in[15];
    float* out = (float*)d_out;

    const int GEMM_SMEM = 2*GSTAGE + 1024;
    cudaFuncSetAttribute(k_gemm_mma, cudaFuncAttributeMaxDynamicSharedMemorySize, GEMM_SMEM);

    k_zero<<<2048, 256>>>();
    k_scatter1<<<BB*NN/4, 256>>>(x, loc, idxa, idxat, wt, dws);
    k_invcnt<<<(BB*HWC)/256, 256>>>();
    k_dwconv<<<BB*HW2/8, 256>>>(dwc);
    k_scatter2<<<BB*NN/4, 256>>>(loc, idxat, wt);
    k_bn1pack<<<MROWS/64, 256>>>();
    k_foldpack<<<COUT, CC>>>(cw, g1, b1);
    k_gemm_mma<<<(MROWS/128)*(COUT/128), 256, GEMM_SMEM>>>(out);
    k_bn2_apply<<<2048, 256>>>(out, g2, b2);
}